// round 15
// baseline (speedup 1.0000x reference)
#include <cuda_runtime.h>
#include <cuda_bf16.h>
#include <cstdint>

// ============================================================================
// TernaryLinear: out[8192,4096] = x[8192,4096] @ W[4096,4096]^T + bias
//
// R15 = R4 verbatim (best: 3116us; even hi-IMMA / lo-dp4a split, 256 thr,
// 4-stage ring, ~150 regs) + ONE mid-iteration __syncthreads that pins the
// two warp groups in anti-phase:
//   phase 1: warps 0-3 mma || warps 4-7 dp4a   -> sync
//   phase 2: warps 0-3 dp4a || warps 4-7 mma   -> sync
// Without it the phases drift (mma issue is cheap) and both warps collide on
// the fma pipe ~35% of the time. Barrier cost ~50cyc/iter << recovered time.
// out = s_row * (256*(H@W^T) + (L@W^T)) + bias, all-int accumulation (exact).
// ============================================================================

#define M_DIM 8192
#define N_DIM 4096
#define K_DIM 4096
#define BM 64
#define BN 128
#define BK 128                     // int8 elems per K tile (128 B/row)
#define NKT (K_DIM / BK)           // 32
#define NSTAGE 4
#define A_HI_OFF 0
#define A_LO_OFF 8192
#define B_OFF    16384
#define STAGE_BYTES 32768          // A_hi 8K + A_lo 8K + B 16K
#define SMEM_TOTAL (NSTAGE * STAGE_BYTES)   // 128 KB

// Static device scratch (sanctioned workaround for no-alloc rule)
__device__ __align__(128) int8_t g_xh8[(size_t)M_DIM * K_DIM];
__device__ __align__(128) int8_t g_xl8[(size_t)M_DIM * K_DIM];
__device__ __align__(128) int8_t g_w8 [(size_t)N_DIM * K_DIM];
__device__ __align__(128) float  g_scale[M_DIM];

// ---------------------------------------------------------------------------
// PTX helpers
// ---------------------------------------------------------------------------
__device__ __forceinline__ uint32_t smem_u32(const void* p) {
    uint32_t a;
    asm("{ .reg .u64 t; cvta.to.shared.u64 t, %1; cvt.u32.u64 %0, t; }"
        : "=r"(a) : "l"(p));
    return a;
}

#define CP16(dst, src) \
    asm volatile("cp.async.cg.shared.global [%0], [%1], 16;" \
                 :: "r"((uint32_t)(dst)), "l"(src) : "memory")
#define CP_COMMIT() asm volatile("cp.async.commit_group;" ::: "memory")
#define CP_WAIT2()  asm volatile("cp.async.wait_group 2;" ::: "memory")

#define LDSM4(r0, r1, r2, r3, addr) \
    asm volatile("ldmatrix.sync.aligned.m8n8.x4.shared.b16 {%0,%1,%2,%3}, [%4];" \
                 : "=r"(r0), "=r"(r1), "=r"(r2), "=r"(r3) : "r"(addr))

__device__ __forceinline__ void mma_s8(int c[4], const uint32_t a[4],
                                       uint32_t b0, uint32_t b1) {
    asm volatile(
        "mma.sync.aligned.m16n8k32.row.col.s32.s8.s8.s32 "
        "{%0,%1,%2,%3}, {%4,%5,%6,%7}, {%8,%9}, {%0,%1,%2,%3};"
        : "+r"(c[0]), "+r"(c[1]), "+r"(c[2]), "+r"(c[3])
        : "r"(a[0]), "r"(a[1]), "r"(a[2]), "r"(a[3]), "r"(b0), "r"(b1));
}

// ---------------------------------------------------------------------------
// Merged pre-pass: blocks [0,8192) quantize x rows; [8192, 24576) convert W.
// ---------------------------------------------------------------------------
__global__ void __launch_bounds__(256) quant_all_kernel(const float* __restrict__ x,
                                                        const float* __restrict__ w) {
    const int t = threadIdx.x;
    if (blockIdx.x < M_DIM) {
        const int row = blockIdx.x;
        const float4* xr = reinterpret_cast<const float4*>(x + (size_t)row * K_DIM);
        float4 v[4];
        float amax = 0.f;
#pragma unroll
        for (int p = 0; p < 4; ++p) {
            v[p] = xr[p * 256 + t];
            amax = fmaxf(amax, fmaxf(fmaxf(fabsf(v[p].x), fabsf(v[p].y)),
                                     fmaxf(fabsf(v[p].z), fabsf(v[p].w))));
        }
#pragma unroll
        for (int o = 16; o; o >>= 1)
            amax = fmaxf(amax, __shfl_xor_sync(0xFFFFFFFFu, amax, o));

        __shared__ float smax[8];
        if ((t & 31) == 0) smax[t >> 5] = amax;
        __syncthreads();
        float bmax = fmaxf(fmaxf(fmaxf(smax[0], smax[1]), fmaxf(smax[2], smax[3])),
                           fmaxf(fmaxf(smax[4], smax[5]), fmaxf(smax[6], smax[7])));

        const float inv = (bmax > 0.f) ? (32639.f / bmax) : 0.f;
        if (t == 0) g_scale[row] = (bmax > 0.f) ? (bmax / 32639.f) : 0.f;

        char4* hp = reinterpret_cast<char4*>(g_xh8 + (size_t)row * K_DIM);
        char4* lp = reinterpret_cast<char4*>(g_xl8 + (size_t)row * K_DIM);
#pragma unroll
        for (int p = 0; p < 4; ++p) {
            int q0 = __float2int_rn(v[p].x * inv);
            int q1 = __float2int_rn(v[p].y * inv);
            int q2 = __float2int_rn(v[p].z * inv);
            int q3 = __float2int_rn(v[p].w * inv);
            int h0 = (q0 + 128) >> 8, h1 = (q1 + 128) >> 8;
            int h2 = (q2 + 128) >> 8, h3 = (q3 + 128) >> 8;
            char4 hc = make_char4((char)h0, (char)h1, (char)h2, (char)h3);
            char4 lc = make_char4((char)(q0 - (h0 << 8)), (char)(q1 - (h1 << 8)),
                                  (char)(q2 - (h2 << 8)), (char)(q3 - (h3 << 8)));
            hp[p * 256 + t] = hc;
            lp[p * 256 + t] = lc;
        }
    } else {
        size_t i = (size_t)(blockIdx.x - M_DIM) * 256 + t;   // float4 index
        float4 v = reinterpret_cast<const float4*>(w)[i];
        char4 c = make_char4((char)__float2int_rn(v.x), (char)__float2int_rn(v.y),
                             (char)__float2int_rn(v.z), (char)__float2int_rn(v.w));
        reinterpret_cast<char4*>(g_w8)[i] = c;
    }
}

// ---------------------------------------------------------------------------
// Main hybrid GEMM. CTA 64x128, 256 thr = 8 warps.
//   hi (IMMA): warps 2m x 4n, warp tile 32x32, accH[2][4][4], 32 mma/iter.
//   lo (dp4a): per-warp 8 rows (wid+8i, broadcast A) x 128 cols (lane+32j),
//              accLo[8][4], 1024 dp4a/iter.
// Barrier-enforced anti-phase per iter; 4-stage cp.async ring, distance 3.
// ---------------------------------------------------------------------------
__global__ void __launch_bounds__(256, 1)
gemm_s8_kernel(const float* __restrict__ bias, float* __restrict__ out) {
    extern __shared__ char smem[];
    const uint32_t sb = smem_u32(smem);
    const int tid = threadIdx.x;
    const int lane = tid & 31;
    const int wid = tid >> 5;
    const int wm = wid >> 2;           // 0..1
    const int wn = wid & 3;            // 0..3
    const int m0 = blockIdx.y * BM;
    const int n0 = blockIdx.x * BN;

    // --- cp.async mapping (8 x 16B chunks per thread = 32 KB/stage) ---
    const int arow = tid >> 2;
    const int acol = (tid & 3) * 2;
    const int8_t* gH = g_xh8 + (size_t)(m0 + arow) * K_DIM + acol * 16;
    const int8_t* gL = g_xl8 + (size_t)(m0 + arow) * K_DIM + acol * 16;
    const uint32_t aBase = (uint32_t)arow * BK;
    const uint32_t asw0 = aBase + (uint32_t)(((acol + 0) ^ (arow & 7)) << 4);
    const uint32_t asw1 = aBase + (uint32_t)(((acol + 1) ^ (arow & 7)) << 4);
    const int brow = tid >> 1;
    const int bcol = (tid & 1) * 4;
    const int8_t* gW = g_w8 + (size_t)(n0 + brow) * K_DIM + bcol * 16;
    const uint32_t bBase = B_OFF + (uint32_t)brow * BK;
    uint32_t bsw[4];
#pragma unroll
    for (int j = 0; j < 4; ++j)
        bsw[j] = bBase + (uint32_t)(((bcol + j) ^ (brow & 7)) << 4);

#define PREFETCH(it) do {                                                     \
    const int _k = (it) * BK;                                                 \
    const uint32_t _s = sb + (uint32_t)((it) & (NSTAGE - 1)) * STAGE_BYTES;   \
    CP16(_s + A_HI_OFF + asw0, gH + _k);                                      \
    CP16(_s + A_HI_OFF + asw1, gH + _k + 16);                                 \
    CP16(_s + A_LO_OFF + asw0, gL + _k);                                      \
    CP16(_s + A_LO_OFF + asw1, gL + _k + 16);                                 \
    CP16(_s + bsw[0], gW + _k);                                               \
    CP16(_s + bsw[1], gW + _k + 16);                                          \
    CP16(_s + bsw[2], gW + _k + 32);                                          \
    CP16(_s + bsw[3], gW + _k + 48);                                          \
} while (0)

    // --- hi-path ldmatrix lane addressing ---
    const int ag = lane >> 3;
    const int aRow0 = wm * 32 + ((ag & 1) << 3) + (lane & 7);
    const int agc = ag >> 1;
    const int bRow = wn * 32 + lane;
    const uint32_t bRowOff = B_OFF + (uint32_t)bRow * BK;
    const int bRowSw = bRow & 7;

    int accH[2][4][4];
#pragma unroll
    for (int mt = 0; mt < 2; ++mt)
#pragma unroll
        for (int nt = 0; nt < 4; ++nt)
#pragma unroll
            for (int i = 0; i < 4; ++i) accH[mt][nt][i] = 0;

    // --- lo-path setup: rows wid+8i (warp-uniform), cols lane+32j ---
    int accLo[8][4];
#pragma unroll
    for (int i = 0; i < 8; ++i)
#pragma unroll
        for (int j = 0; j < 4; ++j) accLo[i][j] = 0;
    const uint32_t loASw = (uint32_t)(wid & 7);             // warp-uniform
    uint32_t loBOff[4];
#pragma unroll
    for (int j = 0; j < 4; ++j)
        loBOff[j] = B_OFF + (uint32_t)(lane + 32 * j) * BK;
    const uint32_t loBSw = (uint32_t)(lane & 7);

    // --- prologue: fill 3 stages ---
    PREFETCH(0); CP_COMMIT();
    PREFETCH(1); CP_COMMIT();
    PREFETCH(2); CP_COMMIT();

    for (int it = 0; it < NKT; ++it) {
        CP_WAIT2();
        __syncthreads();
        if (it + 3 < NKT) { PREFETCH(it + 3); }
        CP_COMMIT();

        const uint32_t S = sb + (uint32_t)(it & (NSTAGE - 1)) * STAGE_BYTES;

        auto hi_pass = [&]() {
#pragma unroll
            for (int ks = 0; ks < 4; ++ks) {
                uint32_t b0[4], b1[4];
                uint32_t a0 = S + bRowOff + (uint32_t)(((ks * 2)     ^ bRowSw) << 4);
                uint32_t a1 = S + bRowOff + (uint32_t)(((ks * 2 + 1) ^ bRowSw) << 4);
                LDSM4(b0[0], b0[1], b0[2], b0[3], a0);
                LDSM4(b1[0], b1[1], b1[2], b1[3], a1);
                uint32_t ah[2][4];
#pragma unroll
                for (int mt = 0; mt < 2; ++mt) {
                    const int rA = aRow0 + mt * 16;
                    const int cA = ks * 2 + agc;
                    const uint32_t off = (uint32_t)rA * BK +
                                         (uint32_t)((cA ^ (rA & 7)) << 4);
                    LDSM4(ah[mt][0], ah[mt][1], ah[mt][2], ah[mt][3],
                          S + A_HI_OFF + off);
                }
#pragma unroll
                for (int mt = 0; mt < 2; ++mt)
#pragma unroll
                    for (int nt = 0; nt < 4; ++nt)
                        mma_s8(accH[mt][nt], ah[mt], b0[nt], b1[nt]);
            }
        };

        auto lo_pass = [&]() {
#pragma unroll 1
            for (int kc = 0; kc < 8; ++kc) {
                uint4 bw[4];
#pragma unroll
                for (int j = 0; j < 4; ++j)
                    bw[j] = *reinterpret_cast<const uint4*>(
                        smem + (S - sb) + loBOff[j] + ((kc ^ loBSw) << 4));
                uint4 aw[8];
#pragma unroll
                for (int i = 0; i < 8; ++i)
                    aw[i] = *reinterpret_cast<const uint4*>(
                        smem + (S - sb) + A_LO_OFF +
                        (uint32_t)(wid + 8 * i) * BK + ((kc ^ loASw) << 4));
#pragma unroll
                for (int i = 0; i < 8; ++i)
#pragma unroll
                    for (int j = 0; j < 4; ++j) {
                        int acc = accLo[i][j];
                        acc = __dp4a((int)aw[i].x, (int)bw[j].x, acc);
                        acc = __dp4a((int)aw[i].y, (int)bw[j].y, acc);
                        acc = __dp4a((int)aw[i].z, (int)bw[j].z, acc);
                        acc = __dp4a((int)aw[i].w, (int)bw[j].w, acc);
                        accLo[i][j] = acc;
                    }
            }
        };

        // Barrier-enforced anti-phase: no drift, both pipes always fed.
        if (wid < 4) { hi_pass(); } else { lo_pass(); }
        __syncthreads();
        if (wid < 4) { lo_pass(); } else { hi_pass(); }
        __syncthreads();
    }

    // --- stage lo accumulators to smem (64 x 128 int32 = 32 KB) ---
    int* loS = reinterpret_cast<int*>(smem);
#pragma unroll
    for (int i = 0; i < 8; ++i)
#pragma unroll
        for (int j = 0; j < 4; ++j)
            loS[(wid + 8 * i) * BN + lane + 32 * j] = accLo[i][j];
    __syncthreads();

    // --- epilogue: combine hi/lo, scale, bias, store fp32 ---
#pragma unroll
    for (int mt = 0; mt < 2; ++mt) {
        const int rl = wm * 32 + mt * 16 + (lane >> 2);
        const int r0 = m0 + rl;
        const float s0 = g_scale[r0];
        const float s1 = g_scale[r0 + 8];
#pragma unroll
        for (int nt = 0; nt < 4; ++nt) {
            const int cl = wn * 32 + nt * 8 + 2 * (lane & 3);
            const int col = n0 + cl;
            const float bv0 = __ldg(bias + col);
            const float bv1 = __ldg(bias + col + 1);
            const int* h = accH[mt][nt];
            float2 o0, o1;
            o0.x = s0 * (float)(256 * h[0] + loS[rl * BN + cl])       + bv0;
            o0.y = s0 * (float)(256 * h[1] + loS[rl * BN + cl + 1])   + bv1;
            o1.x = s1 * (float)(256 * h[2] + loS[(rl + 8) * BN + cl])     + bv0;
            o1.y = s1 * (float)(256 * h[3] + loS[(rl + 8) * BN + cl + 1]) + bv1;
            *reinterpret_cast<float2*>(out + (size_t)r0 * N_DIM + col) = o0;
            *reinterpret_cast<float2*>(out + (size_t)(r0 + 8) * N_DIM + col) = o1;
        }
    }
#undef PREFETCH
}

// ---------------------------------------------------------------------------
// Launch
// ---------------------------------------------------------------------------
extern "C" void kernel_launch(void* const* d_in, const int* in_sizes, int n_in,
                              void* d_out, int out_size) {
    const float* x    = (const float*)d_in[0];
    const float* w    = (const float*)d_in[1];
    const float* bias = (const float*)d_in[2];
    float* out = (float*)d_out;

    quant_all_kernel<<<M_DIM + (N_DIM * K_DIM / 4) / 256, 256>>>(x, w);

    cudaFuncSetAttribute(gemm_s8_kernel,
                         cudaFuncAttributeMaxDynamicSharedMemorySize, SMEM_TOTAL);
    dim3 grid(N_DIM / BN, M_DIM / BM);   // (32, 128): n fastest -> W L2-resident
    gemm_s8_kernel<<<grid, 256, SMEM_TOTAL>>>(bias, out);
}

// round 16
// speedup vs baseline: 1.2861x; 1.2861x over previous
#include <cuda_runtime.h>
#include <cuda_bf16.h>
#include <cstdint>

// ============================================================================
// TernaryLinear: out[8192,4096] = x[8192,4096] @ W[4096,4096]^T + bias
//
// R16: PURE dp4a, correct register regime. Measured across R4/R5/R8: dp4a
// rt_SMSP ~= 0.9-1.0 (128 MAC/cyc/SMSP) when regs are uncapped; fallback
// IMMA is only 64 MAC/cyc. Pure-dp4a floor = 4096 cyc/iter/SMSP on ONE
// pipe == R4's tensor floor, but with zero cross-pipe coordination loss.
// (R13's pure-dp4a failure was the 128-reg cap at 512 thr, not the pipe.)
// 256 thr / 8 warps / 2 per SMSP; warp w owns rows {w+8i}; per kc the bw
// column loads are SHARED by hi and lo passes; epilogue needs no staging.
// out = s_row * (256*hi + lo) + bias, all-int accumulation (exact).
// ============================================================================

#define M_DIM 8192
#define N_DIM 4096
#define K_DIM 4096
#define BM 64
#define BN 128
#define BK 128                     // int8 elems per K tile (128 B/row)
#define NKT (K_DIM / BK)           // 32
#define NSTAGE 4
#define A_HI_OFF 0
#define A_LO_OFF 8192
#define B_OFF    16384
#define STAGE_BYTES 32768          // A_hi 8K + A_lo 8K + B 16K
#define SMEM_TOTAL (NSTAGE * STAGE_BYTES)   // 128 KB

// Static device scratch (sanctioned workaround for no-alloc rule)
__device__ __align__(128) int8_t g_xh8[(size_t)M_DIM * K_DIM];
__device__ __align__(128) int8_t g_xl8[(size_t)M_DIM * K_DIM];
__device__ __align__(128) int8_t g_w8 [(size_t)N_DIM * K_DIM];
__device__ __align__(128) float  g_scale[M_DIM];

// ---------------------------------------------------------------------------
// PTX helpers
// ---------------------------------------------------------------------------
__device__ __forceinline__ uint32_t smem_u32(const void* p) {
    uint32_t a;
    asm("{ .reg .u64 t; cvta.to.shared.u64 t, %1; cvt.u32.u64 %0, t; }"
        : "=r"(a) : "l"(p));
    return a;
}

#define CP16(dst, src) \
    asm volatile("cp.async.cg.shared.global [%0], [%1], 16;" \
                 :: "r"((uint32_t)(dst)), "l"(src) : "memory")
#define CP_COMMIT() asm volatile("cp.async.commit_group;" ::: "memory")
#define CP_WAIT1()  asm volatile("cp.async.wait_group 1;" ::: "memory")

// ---------------------------------------------------------------------------
// Merged pre-pass: blocks [0,8192) quantize x rows; [8192, 24576) convert W.
// ---------------------------------------------------------------------------
__global__ void __launch_bounds__(256) quant_all_kernel(const float* __restrict__ x,
                                                        const float* __restrict__ w) {
    const int t = threadIdx.x;
    if (blockIdx.x < M_DIM) {
        const int row = blockIdx.x;
        const float4* xr = reinterpret_cast<const float4*>(x + (size_t)row * K_DIM);
        float4 v[4];
        float amax = 0.f;
#pragma unroll
        for (int p = 0; p < 4; ++p) {
            v[p] = xr[p * 256 + t];
            amax = fmaxf(amax, fmaxf(fmaxf(fabsf(v[p].x), fabsf(v[p].y)),
                                     fmaxf(fabsf(v[p].z), fabsf(v[p].w))));
        }
#pragma unroll
        for (int o = 16; o; o >>= 1)
            amax = fmaxf(amax, __shfl_xor_sync(0xFFFFFFFFu, amax, o));

        __shared__ float smax[8];
        if ((t & 31) == 0) smax[t >> 5] = amax;
        __syncthreads();
        float bmax = fmaxf(fmaxf(fmaxf(smax[0], smax[1]), fmaxf(smax[2], smax[3])),
                           fmaxf(fmaxf(smax[4], smax[5]), fmaxf(smax[6], smax[7])));

        const float inv = (bmax > 0.f) ? (32639.f / bmax) : 0.f;
        if (t == 0) g_scale[row] = (bmax > 0.f) ? (bmax / 32639.f) : 0.f;

        char4* hp = reinterpret_cast<char4*>(g_xh8 + (size_t)row * K_DIM);
        char4* lp = reinterpret_cast<char4*>(g_xl8 + (size_t)row * K_DIM);
#pragma unroll
        for (int p = 0; p < 4; ++p) {
            int q0 = __float2int_rn(v[p].x * inv);
            int q1 = __float2int_rn(v[p].y * inv);
            int q2 = __float2int_rn(v[p].z * inv);
            int q3 = __float2int_rn(v[p].w * inv);
            int h0 = (q0 + 128) >> 8, h1 = (q1 + 128) >> 8;
            int h2 = (q2 + 128) >> 8, h3 = (q3 + 128) >> 8;
            char4 hc = make_char4((char)h0, (char)h1, (char)h2, (char)h3);
            char4 lc = make_char4((char)(q0 - (h0 << 8)), (char)(q1 - (h1 << 8)),
                                  (char)(q2 - (h2 << 8)), (char)(q3 - (h3 << 8)));
            hp[p * 256 + t] = hc;
            lp[p * 256 + t] = lc;
        }
    } else {
        size_t i = (size_t)(blockIdx.x - M_DIM) * 256 + t;   // float4 index
        float4 v = reinterpret_cast<const float4*>(w)[i];
        char4 c = make_char4((char)__float2int_rn(v.x), (char)__float2int_rn(v.y),
                             (char)__float2int_rn(v.z), (char)__float2int_rn(v.w));
        reinterpret_cast<char4*>(g_w8)[i] = c;
    }
}

// ---------------------------------------------------------------------------
// Main pure-dp4a GEMM. CTA 64x128, 256 thr = 8 warps, 2 per SMSP.
// Warp w owns rows {w+8i, i=0..7} for BOTH hi and lo. Lane owns cols
// lane+32j. Per kc: 4 per-lane bw loads (shared hi/lo) + 8 hi-broadcast +
// 8 lo-broadcast A loads -> 256 dp4a. 2048 dp4a/warp/iter.
// 4-stage cp.async ring, prefetch distance 2, one __syncthreads per iter.
// ---------------------------------------------------------------------------
__global__ void __launch_bounds__(256, 1)
gemm_dp4a_kernel(const float* __restrict__ bias, float* __restrict__ out) {
    extern __shared__ char smem[];
    const uint32_t sb = smem_u32(smem);
    const int tid = threadIdx.x;
    const int lane = tid & 31;
    const int wid = tid >> 5;
    const int m0 = blockIdx.y * BM;
    const int n0 = blockIdx.x * BN;

    // --- cp.async mapping (8 x 16B chunks per thread = 32 KB/stage) ---
    const int arow = tid >> 2;
    const int acol = (tid & 3) * 2;
    const int8_t* gH = g_xh8 + (size_t)(m0 + arow) * K_DIM + acol * 16;
    const int8_t* gL = g_xl8 + (size_t)(m0 + arow) * K_DIM + acol * 16;
    const uint32_t aBase = (uint32_t)arow * BK;
    const uint32_t asw0 = aBase + (uint32_t)(((acol + 0) ^ (arow & 7)) << 4);
    const uint32_t asw1 = aBase + (uint32_t)(((acol + 1) ^ (arow & 7)) << 4);
    const int brow = tid >> 1;
    const int bcol = (tid & 1) * 4;
    const int8_t* gW = g_w8 + (size_t)(n0 + brow) * K_DIM + bcol * 16;
    const uint32_t bBase = B_OFF + (uint32_t)brow * BK;
    uint32_t bsw[4];
#pragma unroll
    for (int j = 0; j < 4; ++j)
        bsw[j] = bBase + (uint32_t)(((bcol + j) ^ (brow & 7)) << 4);

#define PREFETCH(it) do {                                                     \
    const int _k = (it) * BK;                                                 \
    const uint32_t _s = sb + (uint32_t)((it) & (NSTAGE - 1)) * STAGE_BYTES;   \
    CP16(_s + A_HI_OFF + asw0, gH + _k);                                      \
    CP16(_s + A_HI_OFF + asw1, gH + _k + 16);                                 \
    CP16(_s + A_LO_OFF + asw0, gL + _k);                                      \
    CP16(_s + A_LO_OFF + asw1, gL + _k + 16);                                 \
    CP16(_s + bsw[0], gW + _k);                                               \
    CP16(_s + bsw[1], gW + _k + 16);                                          \
    CP16(_s + bsw[2], gW + _k + 32);                                          \
    CP16(_s + bsw[3], gW + _k + 48);                                          \
} while (0)

    // --- dp4a addressing: rows wid+8i (warp-uniform A), cols lane+32j ---
    int accH[8][4], accLo[8][4];
#pragma unroll
    for (int i = 0; i < 8; ++i)
#pragma unroll
        for (int j = 0; j < 4; ++j) { accH[i][j] = 0; accLo[i][j] = 0; }

    const uint32_t aSw = (uint32_t)(wid & 7);               // row&7, warp-uniform
    uint32_t bOff[4];
#pragma unroll
    for (int j = 0; j < 4; ++j)
        bOff[j] = B_OFF + (uint32_t)(lane + 32 * j) * BK;
    const uint32_t bSw = (uint32_t)(lane & 7);

    // --- prologue: fill 2 stages (prefetch distance 2) ---
    PREFETCH(0); CP_COMMIT();
    PREFETCH(1); CP_COMMIT();

    for (int it = 0; it < NKT; ++it) {
        CP_WAIT1();            // stage `it` resident (1 group still in flight)
        __syncthreads();       // visibility + WAR for stage (it+2)&3
        if (it + 2 < NKT) { PREFETCH(it + 2); }
        CP_COMMIT();

        const uint32_t So = (uint32_t)(it & (NSTAGE - 1)) * STAGE_BYTES;

#pragma unroll 2
        for (int kc = 0; kc < 8; ++kc) {
            uint4 bw[4];
#pragma unroll
            for (int j = 0; j < 4; ++j)
                bw[j] = *reinterpret_cast<const uint4*>(
                    smem + So + bOff[j] + (((uint32_t)kc ^ bSw) << 4));
            const uint32_t aCol = (((uint32_t)kc ^ aSw) << 4);
#pragma unroll
            for (int i = 0; i < 8; ++i) {
                const uint32_t rowOff = (uint32_t)(wid + 8 * i) * BK + aCol;
                const uint4 ah = *reinterpret_cast<const uint4*>(
                    smem + So + A_HI_OFF + rowOff);
#pragma unroll
                for (int j = 0; j < 4; ++j) {
                    int a = accH[i][j];
                    a = __dp4a((int)ah.x, (int)bw[j].x, a);
                    a = __dp4a((int)ah.y, (int)bw[j].y, a);
                    a = __dp4a((int)ah.z, (int)bw[j].z, a);
                    a = __dp4a((int)ah.w, (int)bw[j].w, a);
                    accH[i][j] = a;
                }
                const uint4 al = *reinterpret_cast<const uint4*>(
                    smem + So + A_LO_OFF + rowOff);
#pragma unroll
                for (int j = 0; j < 4; ++j) {
                    int a = accLo[i][j];
                    a = __dp4a((int)al.x, (int)bw[j].x, a);
                    a = __dp4a((int)al.y, (int)bw[j].y, a);
                    a = __dp4a((int)al.z, (int)bw[j].z, a);
                    a = __dp4a((int)al.w, (int)bw[j].w, a);
                    accLo[i][j] = a;
                }
            }
        }
    }

    // --- epilogue: hi and lo in-warp -> direct combine, no staging ---
    float bv[4];
#pragma unroll
    for (int j = 0; j < 4; ++j)
        bv[j] = __ldg(bias + n0 + lane + 32 * j);
#pragma unroll
    for (int i = 0; i < 8; ++i) {
        const int r0 = m0 + wid + 8 * i;
        const float s = g_scale[r0];
        float* op = out + (size_t)r0 * N_DIM + n0;
#pragma unroll
        for (int j = 0; j < 4; ++j)
            op[lane + 32 * j] = s * (float)(256 * accH[i][j] + accLo[i][j]) + bv[j];
    }
#undef PREFETCH
}

// ---------------------------------------------------------------------------
// Launch
// ---------------------------------------------------------------------------
extern "C" void kernel_launch(void* const* d_in, const int* in_sizes, int n_in,
                              void* d_out, int out_size) {
    const float* x    = (const float*)d_in[0];
    const float* w    = (const float*)d_in[1];
    const float* bias = (const float*)d_in[2];
    float* out = (float*)d_out;

    quant_all_kernel<<<M_DIM + (N_DIM * K_DIM / 4) / 256, 256>>>(x, w);

    cudaFuncSetAttribute(gemm_dp4a_kernel,
                         cudaFuncAttributeMaxDynamicSharedMemorySize, SMEM_TOTAL);
    dim3 grid(N_DIM / BN, M_DIM / BM);   // (32, 128): n fastest -> W L2-resident
    gemm_dp4a_kernel<<<grid, 256, SMEM_TOTAL>>>(bias, out);
}

// round 17
// speedup vs baseline: 1.4804x; 1.1511x over previous
#include <cuda_runtime.h>
#include <cuda_bf16.h>
#include <cstdint>

// ============================================================================
// TernaryLinear: out[8192,4096] = x[8192,4096] @ W[4096,4096]^T + bias
//
// R17: two co-resident 128-thread CTAs per SM, barrier-decoupled.
// Rates (measured): IMMA 64 MAC/cyc/SMSP (tensor), dp4a 64 MAC/cyc/SMSP
// (fma). Even hi/lo split as R4. Each SMSP hosts 1 warp from each CTA;
// CTAs share no barriers, so one CTA's sync/convoy stalls are filled by the
// other. Per-SM ticket (atomicAdd on %smid) puts co-resident CTAs in
// opposite hi/lo phase. Tile 64x64, 96KB smem/CTA, launch_bounds(128,2).
// out = s_row * (256*(H@W^T) + (L@W^T)) + bias, all-int accumulation.
// ============================================================================

#define M_DIM 8192
#define N_DIM 4096
#define K_DIM 4096
#define BM 64
#define BN 64
#define BK 128                     // int8 elems per K tile (128 B/row)
#define NKT (K_DIM / BK)           // 32
#define NSTAGE 4
#define A_HI_OFF 0
#define A_LO_OFF 8192
#define B_OFF    16384
#define STAGE_BYTES 24576          // A_hi 8K + A_lo 8K + B 8K
#define SMEM_TOTAL (NSTAGE * STAGE_BYTES)   // 96 KB

// Static device scratch (sanctioned workaround for no-alloc rule)
__device__ __align__(128) int8_t g_xh8[(size_t)M_DIM * K_DIM];
__device__ __align__(128) int8_t g_xl8[(size_t)M_DIM * K_DIM];
__device__ __align__(128) int8_t g_w8 [(size_t)N_DIM * K_DIM];
__device__ __align__(128) float  g_scale[M_DIM];
__device__ unsigned g_ticket[256];   // per-SM arrival counter (zero-init)

// ---------------------------------------------------------------------------
// PTX helpers
// ---------------------------------------------------------------------------
__device__ __forceinline__ uint32_t smem_u32(const void* p) {
    uint32_t a;
    asm("{ .reg .u64 t; cvta.to.shared.u64 t, %1; cvt.u32.u64 %0, t; }"
        : "=r"(a) : "l"(p));
    return a;
}

#define CP16(dst, src) \
    asm volatile("cp.async.cg.shared.global [%0], [%1], 16;" \
                 :: "r"((uint32_t)(dst)), "l"(src) : "memory")
#define CP_COMMIT() asm volatile("cp.async.commit_group;" ::: "memory")
#define CP_WAIT2()  asm volatile("cp.async.wait_group 2;" ::: "memory")

#define LDSM4(r0, r1, r2, r3, addr) \
    asm volatile("ldmatrix.sync.aligned.m8n8.x4.shared.b16 {%0,%1,%2,%3}, [%4];" \
                 : "=r"(r0), "=r"(r1), "=r"(r2), "=r"(r3) : "r"(addr))

__device__ __forceinline__ void mma_s8(int c[4], const uint32_t a[4],
                                       uint32_t b0, uint32_t b1) {
    asm volatile(
        "mma.sync.aligned.m16n8k32.row.col.s32.s8.s8.s32 "
        "{%0,%1,%2,%3}, {%4,%5,%6,%7}, {%8,%9}, {%0,%1,%2,%3};"
        : "+r"(c[0]), "+r"(c[1]), "+r"(c[2]), "+r"(c[3])
        : "r"(a[0]), "r"(a[1]), "r"(a[2]), "r"(a[3]), "r"(b0), "r"(b1));
}

// ---------------------------------------------------------------------------
// Merged pre-pass: blocks [0,8192) quantize x rows; [8192, 24576) convert W.
// ---------------------------------------------------------------------------
__global__ void __launch_bounds__(256) quant_all_kernel(const float* __restrict__ x,
                                                        const float* __restrict__ w) {
    const int t = threadIdx.x;
    if (blockIdx.x < M_DIM) {
        const int row = blockIdx.x;
        const float4* xr = reinterpret_cast<const float4*>(x + (size_t)row * K_DIM);
        float4 v[4];
        float amax = 0.f;
#pragma unroll
        for (int p = 0; p < 4; ++p) {
            v[p] = xr[p * 256 + t];
            amax = fmaxf(amax, fmaxf(fmaxf(fabsf(v[p].x), fabsf(v[p].y)),
                                     fmaxf(fabsf(v[p].z), fabsf(v[p].w))));
        }
#pragma unroll
        for (int o = 16; o; o >>= 1)
            amax = fmaxf(amax, __shfl_xor_sync(0xFFFFFFFFu, amax, o));

        __shared__ float smax[8];
        if ((t & 31) == 0) smax[t >> 5] = amax;
        __syncthreads();
        float bmax = fmaxf(fmaxf(fmaxf(smax[0], smax[1]), fmaxf(smax[2], smax[3])),
                           fmaxf(fmaxf(smax[4], smax[5]), fmaxf(smax[6], smax[7])));

        const float inv = (bmax > 0.f) ? (32639.f / bmax) : 0.f;
        if (t == 0) g_scale[row] = (bmax > 0.f) ? (bmax / 32639.f) : 0.f;

        char4* hp = reinterpret_cast<char4*>(g_xh8 + (size_t)row * K_DIM);
        char4* lp = reinterpret_cast<char4*>(g_xl8 + (size_t)row * K_DIM);
#pragma unroll
        for (int p = 0; p < 4; ++p) {
            int q0 = __float2int_rn(v[p].x * inv);
            int q1 = __float2int_rn(v[p].y * inv);
            int q2 = __float2int_rn(v[p].z * inv);
            int q3 = __float2int_rn(v[p].w * inv);
            int h0 = (q0 + 128) >> 8, h1 = (q1 + 128) >> 8;
            int h2 = (q2 + 128) >> 8, h3 = (q3 + 128) >> 8;
            char4 hc = make_char4((char)h0, (char)h1, (char)h2, (char)h3);
            char4 lc = make_char4((char)(q0 - (h0 << 8)), (char)(q1 - (h1 << 8)),
                                  (char)(q2 - (h2 << 8)), (char)(q3 - (h3 << 8)));
            hp[p * 256 + t] = hc;
            lp[p * 256 + t] = lc;
        }
    } else {
        size_t i = (size_t)(blockIdx.x - M_DIM) * 256 + t;   // float4 index
        float4 v = reinterpret_cast<const float4*>(w)[i];
        char4 c = make_char4((char)__float2int_rn(v.x), (char)__float2int_rn(v.y),
                             (char)__float2int_rn(v.z), (char)__float2int_rn(v.w));
        reinterpret_cast<char4*>(g_w8)[i] = c;
    }
}

// ---------------------------------------------------------------------------
// Main hybrid GEMM. CTA 64x64, 128 thr = 4 warps (one per SMSP).
//   hi (IMMA): warps 2m x 2n, warp tile 32x32, accH[2][4][4], 32 mma/iter.
//   lo (dp4a): rows wid+4i (i=0..15, broadcast A), cols lane+32j (j=0..1),
//              accLo[16][2], 1024 dp4a/iter.
// Phase by per-SM arrival ticket: co-resident CTAs run opposite hi/lo order.
// 4-stage cp.async ring, distance 3, one __syncthreads per iter (R4 scheme).
// ---------------------------------------------------------------------------
__global__ void __launch_bounds__(128, 2)
gemm_s8_kernel(const float* __restrict__ bias, float* __restrict__ out) {
    extern __shared__ char smem[];
    __shared__ unsigned s_phase;
    const uint32_t sb = smem_u32(smem);
    const int tid = threadIdx.x;
    const int lane = tid & 31;
    const int wid = tid >> 5;          // 0..3, SMSP = wid
    const int wm = wid >> 1;           // 0..1 (m half)
    const int wn = wid & 1;            // 0..1 (n half)
    const int m0 = blockIdx.y * BM;
    const int n0 = blockIdx.x * BN;

    // per-SM arrival ticket -> phase (co-resident CTAs get opposite parity)
    if (tid == 0) {
        uint32_t smid;
        asm volatile("mov.u32 %0, %%smid;" : "=r"(smid));
        s_phase = atomicAdd(&g_ticket[smid & 255], 1u) & 1u;
    }

    // --- cp.async mapping: 12 x 16B chunks per thread (24 KB / 128 thr) ---
    // A (hi & lo) and B: 64 rows x 8 chunks each; thread t -> row t>>1,
    // chunks (t&1)*4 + {0..3}.
    const int prow = tid >> 1;
    const int pc0 = (tid & 1) * 4;
    const int8_t* gH = g_xh8 + (size_t)(m0 + prow) * K_DIM + pc0 * 16;
    const int8_t* gL = g_xl8 + (size_t)(m0 + prow) * K_DIM + pc0 * 16;
    const int8_t* gW = g_w8  + (size_t)(n0 + prow) * K_DIM + pc0 * 16;
    const uint32_t pBase = (uint32_t)prow * BK;
    const uint32_t pr7 = (uint32_t)(prow & 7);
    uint32_t psw[4];
#pragma unroll
    for (int c = 0; c < 4; ++c)
        psw[c] = pBase + ((((uint32_t)(pc0 + c)) ^ pr7) << 4);

#define PREFETCH(it) do {                                                     \
    const int _k = (it) * BK;                                                 \
    const uint32_t _s = sb + (uint32_t)((it) & (NSTAGE - 1)) * STAGE_BYTES;   \
    _Pragma("unroll")                                                         \
    for (int _c = 0; _c < 4; ++_c) {                                         \
        CP16(_s + A_HI_OFF + psw[_c], gH + _k + _c * 16);                     \
        CP16(_s + A_LO_OFF + psw[_c], gL + _k + _c * 16);                     \
        CP16(_s + B_OFF    + psw[_c], gW + _k + _c * 16);                     \
    }                                                                         \
} while (0)

    // --- hi-path ldmatrix lane addressing ---
    const int ag = lane >> 3;
    const int aRow0 = wm * 32 + ((ag & 1) << 3) + (lane & 7);
    const int agc = ag >> 1;
    const int bRow = wn * 32 + lane;
    const uint32_t bRowOff = B_OFF + (uint32_t)bRow * BK;
    const int bRowSw = bRow & 7;

    int accH[2][4][4];
#pragma unroll
    for (int mt = 0; mt < 2; ++mt)
#pragma unroll
        for (int nt = 0; nt < 4; ++nt)
#pragma unroll
            for (int i = 0; i < 4; ++i) accH[mt][nt][i] = 0;

    // --- lo-path setup: rows wid+4i (warp-uniform A), cols lane+32j ---
    int accLo[16][2];
#pragma unroll
    for (int i = 0; i < 16; ++i) { accLo[i][0] = 0; accLo[i][1] = 0; }
    uint32_t loBOff[2];
#pragma unroll
    for (int j = 0; j < 2; ++j)
        loBOff[j] = B_OFF + (uint32_t)(lane + 32 * j) * BK;
    const uint32_t loBSw = (uint32_t)(lane & 7);

    // --- prologue: fill 3 stages ---
    PREFETCH(0); CP_COMMIT();
    PREFETCH(1); CP_COMMIT();
    PREFETCH(2); CP_COMMIT();
    __syncthreads();                 // publish s_phase (overlaps prefetch)
    const int phase = (int)s_phase;

    for (int it = 0; it < NKT; ++it) {
        CP_WAIT2();
        __syncthreads();
        if (it + 3 < NKT) { PREFETCH(it + 3); }
        CP_COMMIT();

        const uint32_t So = (uint32_t)(it & (NSTAGE - 1)) * STAGE_BYTES;
        const uint32_t S = sb + So;

        auto hi_pass = [&]() {
#pragma unroll
            for (int ks = 0; ks < 4; ++ks) {
                uint32_t b0[4], b1[4];
                uint32_t a0 = S + bRowOff + (uint32_t)(((ks * 2)     ^ bRowSw) << 4);
                uint32_t a1 = S + bRowOff + (uint32_t)(((ks * 2 + 1) ^ bRowSw) << 4);
                LDSM4(b0[0], b0[1], b0[2], b0[3], a0);
                LDSM4(b1[0], b1[1], b1[2], b1[3], a1);
                uint32_t ah[2][4];
#pragma unroll
                for (int mt = 0; mt < 2; ++mt) {
                    const int rA = aRow0 + mt * 16;
                    const int cA = ks * 2 + agc;
                    const uint32_t off = (uint32_t)rA * BK +
                                         (uint32_t)((cA ^ (rA & 7)) << 4);
                    LDSM4(ah[mt][0], ah[mt][1], ah[mt][2], ah[mt][3],
                          S + A_HI_OFF + off);
                }
#pragma unroll
                for (int mt = 0; mt < 2; ++mt)
#pragma unroll
                    for (int nt = 0; nt < 4; ++nt)
                        mma_s8(accH[mt][nt], ah[mt], b0[nt], b1[nt]);
            }
        };

        auto lo_pass = [&]() {
#pragma unroll 1
            for (int kc = 0; kc < 8; ++kc) {
                uint4 bw[2];
#pragma unroll
                for (int j = 0; j < 2; ++j)
                    bw[j] = *reinterpret_cast<const uint4*>(
                        smem + So + loBOff[j] + (((uint32_t)kc ^ loBSw) << 4));
#pragma unroll
                for (int i = 0; i < 16; ++i) {
                    const int rr = wid + 4 * i;
                    const uint4 aw = *reinterpret_cast<const uint4*>(
                        smem + So + A_LO_OFF + (uint32_t)rr * BK +
                        (((uint32_t)kc ^ (uint32_t)(rr & 7)) << 4));
#pragma unroll
                    for (int j = 0; j < 2; ++j) {
                        int a = accLo[i][j];
                        a = __dp4a((int)aw.x, (int)bw[j].x, a);
                        a = __dp4a((int)aw.y, (int)bw[j].y, a);
                        a = __dp4a((int)aw.z, (int)bw[j].z, a);
                        a = __dp4a((int)aw.w, (int)bw[j].w, a);
                        accLo[i][j] = a;
                    }
                }
            }
        };

        // Opposite order in the co-resident CTA (per-SM ticket parity):
        // SMSP k hosts a hi-phase warp from one CTA and a lo-phase warp
        // from the other -> both pipes fed without shared barriers.
        if (phase == 0) { hi_pass(); lo_pass(); }
        else            { lo_pass(); hi_pass(); }
    }

    // --- stage lo accumulators to smem (64 x 64 int32 = 16 KB) ---
    __syncthreads();           // all mainloop smem reads done before reuse
    int* loS = reinterpret_cast<int*>(smem);
#pragma unroll
    for (int i = 0; i < 16; ++i) {
        loS[(wid + 4 * i) * BN + lane]      = accLo[i][0];
        loS[(wid + 4 * i) * BN + lane + 32] = accLo[i][1];
    }
    __syncthreads();

    // --- epilogue: combine hi/lo, scale, bias, store fp32 ---
#pragma unroll
    for (int mt = 0; mt < 2; ++mt) {
        const int rl = wm * 32 + mt * 16 + (lane >> 2);
        const int r0 = m0 + rl;
        const float s0 = g_scale[r0];
        const float s1 = g_scale[r0 + 8];
#pragma unroll
        for (int nt = 0; nt < 4; ++nt) {
            const int cl = wn * 32 + nt * 8 + 2 * (lane & 3);
            const int col = n0 + cl;
            const float bv0 = __ldg(bias + col);
            const float bv1 = __ldg(bias + col + 1);
            const int* h = accH[mt][nt];
            float2 o0, o1;
            o0.x = s0 * (float)(256 * h[0] + loS[rl * BN + cl])       + bv0;
            o0.y = s0 * (float)(256 * h[1] + loS[rl * BN + cl + 1])   + bv1;
            o1.x = s1 * (float)(256 * h[2] + loS[(rl + 8) * BN + cl])     + bv0;
            o1.y = s1 * (float)(256 * h[3] + loS[(rl + 8) * BN + cl + 1]) + bv1;
            *reinterpret_cast<float2*>(out + (size_t)r0 * N_DIM + col) = o0;
            *reinterpret_cast<float2*>(out + (size_t)(r0 + 8) * N_DIM + col) = o1;
        }
    }
#undef PREFETCH
}

// ---------------------------------------------------------------------------
// Launch
// ---------------------------------------------------------------------------
extern "C" void kernel_launch(void* const* d_in, const int* in_sizes, int n_in,
                              void* d_out, int out_size) {
    const float* x    = (const float*)d_in[0];
    const float* w    = (const float*)d_in[1];
    const float* bias = (const float*)d_in[2];
    float* out = (float*)d_out;

    quant_all_kernel<<<M_DIM + (N_DIM * K_DIM / 4) / 256, 256>>>(x, w);

    cudaFuncSetAttribute(gemm_s8_kernel,
                         cudaFuncAttributeMaxDynamicSharedMemorySize, SMEM_TOTAL);
    dim3 grid(N_DIM / BN, M_DIM / BM);   // (64, 128): n fastest -> W L2-resident
    gemm_s8_kernel<<<grid, 128, SMEM_TOTAL>>>(bias, out);
}